// round 2
// baseline (speedup 1.0000x reference)
#include <cuda_runtime.h>
#include <math.h>
#include <stdint.h>

// Problem constants
#define HID   2048
#define NH    16
#define NKV   4
#define HD    128
#define SEQ   1024
#define NB    4
#define NT    4096          // NB*SEQ tokens
#define QKV_N 3072          // (NH + 2*NKV) * HD
#define FFI   8192
#define EPS   1e-6f
#define NEGF  (-1e30f)

// ---------------- scratch (no allocations allowed) ----------------
__device__ float g_h   [(size_t)NT * HID];     // rmsnorm1 output
__device__ float g_qkv [(size_t)NT * QKV_N];   // qkv projection
__device__ float g_aout[(size_t)NT * HID];     // attention output (B,S,H*D)
__device__ float g_h1  [(size_t)NT * HID];     // x + attn@wo
__device__ float g_h2  [(size_t)NT * HID];     // rmsnorm2 output
__device__ float g_gu  [(size_t)NT * 2 * FFI]; // gate/up projection
__device__ float g_act [(size_t)NT * FFI];     // silu(gate)*up

// ---------------- RMSNorm ----------------
__global__ void __launch_bounds__(256) rmsnorm_kernel(const float* __restrict__ x,
                                                      const float* __restrict__ w,
                                                      float* __restrict__ out) {
    const int row = blockIdx.x;
    const int tid = threadIdx.x;
    const float4* xr = (const float4*)(x + (size_t)row * HID);
    const float4* wr = (const float4*)w;
    float4* orow = (float4*)(out + (size_t)row * HID);

    float4 v0 = xr[tid];
    float4 v1 = xr[tid + 256];
    float ss = v0.x*v0.x + v0.y*v0.y + v0.z*v0.z + v0.w*v0.w
             + v1.x*v1.x + v1.y*v1.y + v1.z*v1.z + v1.w*v1.w;

    __shared__ float red[256];
    red[tid] = ss;
    __syncthreads();
    for (int s = 128; s > 0; s >>= 1) {
        if (tid < s) red[tid] += red[tid + s];
        __syncthreads();
    }
    const float inv = rsqrtf(red[0] * (1.0f / HID) + EPS);

    float4 w0 = wr[tid], w1 = wr[tid + 256];
    float4 o0 = make_float4(v0.x*inv*w0.x, v0.y*inv*w0.y, v0.z*inv*w0.z, v0.w*inv*w0.w);
    float4 o1 = make_float4(v1.x*inv*w1.x, v1.y*inv*w1.y, v1.z*inv*w1.z, v1.w*inv*w1.w);
    orow[tid]       = o0;
    orow[tid + 256] = o1;
}

// ---------------- SGEMM: C[M,N] = A[M,K] @ B[K,N] (+R) ----------------
// 128x128 block tile, BK=8, 256 threads, 8x8 microtile.
template <int EPI>
__global__ void __launch_bounds__(256) sgemm_kernel(const float* __restrict__ A,
                                                    const float* __restrict__ B,
                                                    const float* __restrict__ R,
                                                    float* __restrict__ C,
                                                    int M, int N, int K) {
    __shared__ float As[8][128];
    __shared__ float Bs[8][128];

    const int tid = threadIdx.x;
    const int bm = blockIdx.y * 128;
    const int bn = blockIdx.x * 128;

    const int aRow = tid >> 1;             // 0..127
    const int aCol = (tid & 1) << 2;       // 0 or 4
    const int bRow = tid >> 5;             // 0..7
    const int bCol = (tid & 31) << 2;      // 0..124

    const int ty = tid >> 4, tx = tid & 15;
    const int row0 = ty << 3, col0 = tx << 3;

    float acc[8][8];
#pragma unroll
    for (int i = 0; i < 8; i++)
#pragma unroll
        for (int j = 0; j < 8; j++) acc[i][j] = 0.0f;

    const float* Aptr = A + (size_t)(bm + aRow) * K + aCol;
    const float* Bptr = B + (size_t)bRow * N + bn + bCol;

    for (int k0 = 0; k0 < K; k0 += 8) {
        float4 av = *(const float4*)(Aptr + k0);
        float4 bv = *(const float4*)(Bptr + (size_t)k0 * N);
        As[aCol + 0][aRow] = av.x;
        As[aCol + 1][aRow] = av.y;
        As[aCol + 2][aRow] = av.z;
        As[aCol + 3][aRow] = av.w;
        *(float4*)&Bs[bRow][bCol] = bv;
        __syncthreads();

#pragma unroll
        for (int k = 0; k < 8; k++) {
            float4 a0 = *(const float4*)&As[k][row0];
            float4 a1 = *(const float4*)&As[k][row0 + 4];
            float4 b0 = *(const float4*)&Bs[k][col0];
            float4 b1 = *(const float4*)&Bs[k][col0 + 4];
            float ar[8] = {a0.x, a0.y, a0.z, a0.w, a1.x, a1.y, a1.z, a1.w};
            float br[8] = {b0.x, b0.y, b0.z, b0.w, b1.x, b1.y, b1.z, b1.w};
#pragma unroll
            for (int i = 0; i < 8; i++)
#pragma unroll
                for (int j = 0; j < 8; j++)
                    acc[i][j] += ar[i] * br[j];
        }
        __syncthreads();
    }

#pragma unroll
    for (int i = 0; i < 8; i++) {
        size_t off = (size_t)(bm + row0 + i) * N + (bn + col0);
        float4 c0 = make_float4(acc[i][0], acc[i][1], acc[i][2], acc[i][3]);
        float4 c1 = make_float4(acc[i][4], acc[i][5], acc[i][6], acc[i][7]);
        if (EPI == 1) {
            float4 r0v = *(const float4*)(R + off);
            float4 r1v = *(const float4*)(R + off + 4);
            c0.x += r0v.x; c0.y += r0v.y; c0.z += r0v.z; c0.w += r0v.w;
            c1.x += r1v.x; c1.y += r1v.y; c1.z += r1v.z; c1.w += r1v.w;
        }
        *(float4*)(C + off)     = c0;
        *(float4*)(C + off + 4) = c1;
    }
}

// ---------------- RoPE (in-place on q and k heads of qkv) ----------------
__global__ void rope_kernel(float* __restrict__ qkv, const int* __restrict__ pos) {
    const int t  = blockIdx.x;       // 0..NT-1
    const int hh = blockIdx.y;       // 0..NH+NKV-1 (q heads then k heads; offsets contiguous)
    const int i  = threadIdx.x;      // 0..63
    const float p = (float)pos[t & (SEQ - 1)];
    const float inv_freq = powf(10000.0f, -((float)i) / 64.0f);
    float sn, cs;
    sincosf(p * inv_freq, &sn, &cs);
    float* vp = qkv + (size_t)t * QKV_N + hh * HD;
    const float t1 = vp[i];
    const float t2 = vp[i + 64];
    vp[i]      = t1 * cs - t2 * sn;
    vp[i + 64] = t2 * cs + t1 * sn;
}

// ---------------- Flash attention (fp32, causal, GQA) ----------------
// grid (SEQ/64, NH, NB), 256 threads. BM=BN=64, D=128.
#define ATT_SMEM ((3 * 64 * 128 + 64 * 64 + 3 * 64) * 4)

__global__ void __launch_bounds__(256) attn_kernel(const float* __restrict__ qkv,
                                                   float* __restrict__ aout) {
    const int qt = blockIdx.x, h = blockIdx.y, b = blockIdx.z;
    const int kvh = h >> 2;

    extern __shared__ float sm[];
    float* Qs   = sm;                 // [64][128] row-major
    float* Kst  = Qs + 64 * 128;      // [128][64] (d-major, transposed)
    float* Vs   = Kst + 128 * 64;     // [64][128] row-major
    float* Ss   = Vs + 64 * 128;      // [64][64] scores / probs
    float* rowm = Ss + 64 * 64;       // [64]
    float* rowl = rowm + 64;          // [64]
    float* rowa = rowl + 64;          // [64]

    const int tid = threadIdx.x;
    const int q0 = qt * 64;

    // load Q tile
    for (int i = tid; i < 64 * 32; i += 256) {
        int r = i >> 5, c4 = i & 31;
        *(float4*)&Qs[r * 128 + c4 * 4] =
            *(const float4*)(qkv + (size_t)(b * SEQ + q0 + r) * QKV_N + h * HD + c4 * 4);
    }
    if (tid < 64) { rowm[tid] = NEGF; rowl[tid] = 0.0f; }

    const int ty = tid >> 4, tx = tid & 15;
    const int r0 = ty * 4;
    float o[4][8];
#pragma unroll
    for (int a = 0; a < 4; a++)
#pragma unroll
        for (int j = 0; j < 8; j++) o[a][j] = 0.0f;
    __syncthreads();

    const float scale = 0.0883883476483184f;   // 1/sqrt(128)

    for (int kt = 0; kt <= qt; kt++) {
        const int k0 = kt * 64;
        // K tile transposed -> Kst[d][n]
        for (int i = tid; i < 2048; i += 256) {
            int r = i & 63, c4 = i >> 6;
            float4 kk = *(const float4*)(qkv + (size_t)(b * SEQ + k0 + r) * QKV_N
                                         + NH * HD + kvh * HD + c4 * 4);
            int d0 = c4 * 4;
            Kst[(d0 + 0) * 64 + r] = kk.x;
            Kst[(d0 + 1) * 64 + r] = kk.y;
            Kst[(d0 + 2) * 64 + r] = kk.z;
            Kst[(d0 + 3) * 64 + r] = kk.w;
        }
        // V tile row-major
        for (int i = tid; i < 2048; i += 256) {
            int r = i >> 5, c4 = i & 31;
            *(float4*)&Vs[r * 128 + c4 * 4] =
                *(const float4*)(qkv + (size_t)(b * SEQ + k0 + r) * QKV_N
                                 + (NH + NKV) * HD + kvh * HD + c4 * 4);
        }
        __syncthreads();

        // scores: each thread computes 4x4 block (rows r0.., cols tx*4..)
        float s[4][4];
#pragma unroll
        for (int a = 0; a < 4; a++)
#pragma unroll
            for (int j = 0; j < 4; j++) s[a][j] = 0.0f;

#pragma unroll 4
        for (int k = 0; k < 128; k++) {
            float qa[4], kb[4];
#pragma unroll
            for (int a = 0; a < 4; a++) qa[a] = Qs[(r0 + a) * 128 + k];
#pragma unroll
            for (int j = 0; j < 4; j++) kb[j] = Kst[k * 64 + tx * 4 + j];
#pragma unroll
            for (int a = 0; a < 4; a++)
#pragma unroll
                for (int j = 0; j < 4; j++) s[a][j] += qa[a] * kb[j];
        }
        const bool diag = (kt == qt);
#pragma unroll
        for (int a = 0; a < 4; a++)
#pragma unroll
            for (int j = 0; j < 4; j++) {
                float v = s[a][j] * scale;
                if (diag && (r0 + a) < (tx * 4 + j)) v = NEGF;
                Ss[(r0 + a) * 64 + tx * 4 + j] = v;
            }
        __syncthreads();

        // online softmax row update: 4 threads per row
        {
            const int row = tid >> 2, l4 = tid & 3;
            float mx = NEGF;
            for (int c = l4; c < 64; c += 4) mx = fmaxf(mx, Ss[row * 64 + c]);
            mx = fmaxf(mx, __shfl_xor_sync(0xffffffffu, mx, 1));
            mx = fmaxf(mx, __shfl_xor_sync(0xffffffffu, mx, 2));
            const float mold = rowm[row];
            const float mnew = fmaxf(mold, mx);
            float ls = 0.0f;
            for (int c = l4; c < 64; c += 4) {
                float p = expf(Ss[row * 64 + c] - mnew);
                Ss[row * 64 + c] = p;
                ls += p;
            }
            ls += __shfl_xor_sync(0xffffffffu, ls, 1);
            ls += __shfl_xor_sync(0xffffffffu, ls, 2);
            if (l4 == 0) {
                const float alpha = expf(mold - mnew);
                rowa[row] = alpha;
                rowl[row] = rowl[row] * alpha + ls;
                rowm[row] = mnew;
            }
        }
        __syncthreads();

        // rescale o, accumulate P@V (rows r0.., cols tx*8..)
        float al[4];
#pragma unroll
        for (int a = 0; a < 4; a++) al[a] = rowa[r0 + a];
#pragma unroll
        for (int a = 0; a < 4; a++)
#pragma unroll
            for (int j = 0; j < 8; j++) o[a][j] *= al[a];

#pragma unroll 2
        for (int kk = 0; kk < 64; kk++) {
            float p[4];
#pragma unroll
            for (int a = 0; a < 4; a++) p[a] = Ss[(r0 + a) * 64 + kk];
            float4 v0 = *(const float4*)&Vs[kk * 128 + tx * 8];
            float4 v1 = *(const float4*)&Vs[kk * 128 + tx * 8 + 4];
            float vv[8] = {v0.x, v0.y, v0.z, v0.w, v1.x, v1.y, v1.z, v1.w};
#pragma unroll
            for (int a = 0; a < 4; a++)
#pragma unroll
                for (int j = 0; j < 8; j++) o[a][j] += p[a] * vv[j];
        }
        __syncthreads();
    }

    // normalize & write: aout[t][h*128 + d]
    float il[4];
#pragma unroll
    for (int a = 0; a < 4; a++) il[a] = 1.0f / rowl[r0 + a];
#pragma unroll
    for (int a = 0; a < 4; a++) {
        size_t off = (size_t)(b * SEQ + q0 + r0 + a) * HID + h * HD + tx * 8;
        float4 o0 = make_float4(o[a][0] * il[a], o[a][1] * il[a], o[a][2] * il[a], o[a][3] * il[a]);
        float4 o1 = make_float4(o[a][4] * il[a], o[a][5] * il[a], o[a][6] * il[a], o[a][7] * il[a]);
        *(float4*)(aout + off)     = o0;
        *(float4*)(aout + off + 4) = o1;
    }
}

// ---------------- SiLU(gate)*up ----------------
__global__ void __launch_bounds__(256) silu_kernel(const float* __restrict__ gu,
                                                   float* __restrict__ act) {
    size_t idx = (size_t)blockIdx.x * 256 + threadIdx.x;   // over NT*FFI/4
    int row = (int)(idx / (FFI / 4));
    int c   = (int)(idx % (FFI / 4));
    const float4 g = *(const float4*)(gu + (size_t)row * 2 * FFI + c * 4);
    const float4 u = *(const float4*)(gu + (size_t)row * 2 * FFI + FFI + c * 4);
    float4 r;
    r.x = g.x / (1.0f + expf(-g.x)) * u.x;
    r.y = g.y / (1.0f + expf(-g.y)) * u.y;
    r.z = g.z / (1.0f + expf(-g.z)) * u.z;
    r.w = g.w / (1.0f + expf(-g.w)) * u.w;
    *(float4*)(act + (size_t)row * FFI + c * 4) = r;
}

// ---------------- launch ----------------
extern "C" void kernel_launch(void* const* d_in, const int* in_sizes, int n_in,
                              void* d_out, int out_size) {
    const float* x    = (const float*)d_in[0];
    const float* ln1w = (const float*)d_in[1];
    const float* wqkv = (const float*)d_in[2];
    const float* wo   = (const float*)d_in[3];
    const float* ln2w = (const float*)d_in[4];
    const float* wgu  = (const float*)d_in[5];
    const float* wdn  = (const float*)d_in[6];
    const int*   pos  = (const int*)d_in[7];
    float* out = (float*)d_out;

    void *ph, *pqkv, *paout, *ph1, *ph2, *pgu, *pact;
    cudaGetSymbolAddress(&ph,    g_h);
    cudaGetSymbolAddress(&pqkv,  g_qkv);
    cudaGetSymbolAddress(&paout, g_aout);
    cudaGetSymbolAddress(&ph1,   g_h1);
    cudaGetSymbolAddress(&ph2,   g_h2);
    cudaGetSymbolAddress(&pgu,   g_gu);
    cudaGetSymbolAddress(&pact,  g_act);
    float* h    = (float*)ph;
    float* qkv  = (float*)pqkv;
    float* aout = (float*)paout;
    float* h1   = (float*)ph1;
    float* h2   = (float*)ph2;
    float* gu   = (float*)pgu;
    float* act  = (float*)pact;

    cudaFuncSetAttribute(attn_kernel, cudaFuncAttributeMaxDynamicSharedMemorySize, ATT_SMEM);

    // 1. h = rmsnorm(x, ln1_w)
    rmsnorm_kernel<<<NT, 256>>>(x, ln1w, h);
    // 2. qkv = h @ wqkv
    sgemm_kernel<0><<<dim3(QKV_N / 128, NT / 128), 256>>>(h, wqkv, nullptr, qkv, NT, QKV_N, HID);
    // 3. rope(q, k)
    rope_kernel<<<dim3(NT, NH + NKV), 64>>>(qkv, pos);
    // 4. flash attention -> aout
    attn_kernel<<<dim3(SEQ / 64, NH, NB), 256, ATT_SMEM>>>(qkv, aout);
    // 5. h1 = x + aout @ wo
    sgemm_kernel<1><<<dim3(HID / 128, NT / 128), 256>>>(aout, wo, x, h1, NT, HID, HID);
    // 6. h2 = rmsnorm(h1, ln2_w)
    rmsnorm_kernel<<<NT, 256>>>(h1, ln2w, h2);
    // 7. gu = h2 @ w_gate_up
    sgemm_kernel<0><<<dim3(2 * FFI / 128, NT / 128), 256>>>(h2, wgu, nullptr, gu, NT, 2 * FFI, HID);
    // 8. act = silu(gate) * up
    silu_kernel<<<(NT * FFI / 4) / 256, 256>>>(gu, act);
    // 9. out = h1 + act @ w_down
    sgemm_kernel<1><<<dim3(HID / 128, NT / 128), 256>>>(act, wdn, h1, out, NT, HID, FFI);
}

// round 3
// speedup vs baseline: 2.0059x; 2.0059x over previous
#include <cuda_runtime.h>
#include <math.h>
#include <stdint.h>

// Problem constants
#define HID   2048
#define NH    16
#define NKV   4
#define HD    128
#define SEQ   1024
#define NB    4
#define NT    4096          // NB*SEQ tokens
#define QKV_N 3072          // (NH + 2*NKV) * HD
#define FFI   8192
#define EPS   1e-6f
#define NEGF  (-1e30f)

// ---------------- scratch (no allocations allowed) ----------------
__device__ float g_h   [(size_t)NT * HID];     // rmsnorm1 output
__device__ float g_qkv [(size_t)NT * QKV_N];   // qkv projection
__device__ float g_aout[(size_t)NT * HID];     // attention output (B,S,H*D)
__device__ float g_h1  [(size_t)NT * HID];     // x + attn@wo
__device__ float g_h2  [(size_t)NT * HID];     // rmsnorm2 output
__device__ float g_gu  [(size_t)NT * 2 * FFI]; // gate/up projection
__device__ float g_act [(size_t)NT * FFI];     // silu(gate)*up

// ---------------- helpers ----------------
__device__ __forceinline__ uint32_t f2tf(float f) {
    uint32_t u;
    asm("cvt.rna.tf32.f32 %0, %1;" : "=r"(u) : "f"(f));
    return u;
}

__device__ __forceinline__ void mma_tf32(float* d, const uint32_t* a, const uint32_t* b) {
    asm volatile(
        "mma.sync.aligned.m16n8k8.row.col.f32.tf32.tf32.f32 "
        "{%0,%1,%2,%3}, {%4,%5,%6,%7}, {%8,%9}, {%0,%1,%2,%3};\n"
        : "+f"(d[0]), "+f"(d[1]), "+f"(d[2]), "+f"(d[3])
        : "r"(a[0]), "r"(a[1]), "r"(a[2]), "r"(a[3]), "r"(b[0]), "r"(b[1]));
}

__device__ __forceinline__ void cp_async16(void* s, const void* g) {
    uint32_t sa = (uint32_t)__cvta_generic_to_shared(s);
    asm volatile("cp.async.cg.shared.global [%0], [%1], 16;\n" :: "r"(sa), "l"(g));
}

// ---------------- RMSNorm ----------------
__global__ void __launch_bounds__(256) rmsnorm_kernel(const float* __restrict__ x,
                                                      const float* __restrict__ w,
                                                      float* __restrict__ out) {
    const int row = blockIdx.x;
    const int tid = threadIdx.x;
    const float4* xr = (const float4*)(x + (size_t)row * HID);
    const float4* wr = (const float4*)w;
    float4* orow = (float4*)(out + (size_t)row * HID);

    float4 v0 = xr[tid];
    float4 v1 = xr[tid + 256];
    float ss = v0.x*v0.x + v0.y*v0.y + v0.z*v0.z + v0.w*v0.w
             + v1.x*v1.x + v1.y*v1.y + v1.z*v1.z + v1.w*v1.w;

    __shared__ float red[256];
    red[tid] = ss;
    __syncthreads();
    for (int s = 128; s > 0; s >>= 1) {
        if (tid < s) red[tid] += red[tid + s];
        __syncthreads();
    }
    const float inv = rsqrtf(red[0] * (1.0f / HID) + EPS);

    float4 w0 = wr[tid], w1 = wr[tid + 256];
    float4 o0 = make_float4(v0.x*inv*w0.x, v0.y*inv*w0.y, v0.z*inv*w0.z, v0.w*inv*w0.w);
    float4 o1 = make_float4(v1.x*inv*w1.x, v1.y*inv*w1.y, v1.z*inv*w1.z, v1.w*inv*w1.w);
    orow[tid]       = o0;
    orow[tid + 256] = o1;
}

// ---------------- TF32 tensor-core GEMM ----------------
// C[M,N] = A[M,K] @ B[K,N] (+R).  128x128 block, BK=16, 256 threads.
// 8 warps in 2x4 (m x n) grid, each warp owns a 64x32 tile =
// 4x4 grid of m16n8k8 mma fragments. cp.async double buffering.
template <int EPI>
__global__ void __launch_bounds__(256) tf32gemm_kernel(const float* __restrict__ A,
                                                       const float* __restrict__ B,
                                                       const float* __restrict__ R,
                                                       float* __restrict__ C,
                                                       int M, int N, int K) {
    __shared__ float As[2][128][20];   // [m][k], pitch 20 -> conflict-free frag loads
    __shared__ float Bs[2][16][136];   // [k][n], pitch 136 -> conflict-free frag loads

    const int tid  = threadIdx.x;
    const int bm   = blockIdx.y * 128;
    const int bn   = blockIdx.x * 128;
    const int lane = tid & 31;
    const int warp = tid >> 5;
    const int g = lane >> 2;           // group id 0..7
    const int c = lane & 3;            // thread-in-group 0..3
    const int wm = (warp >> 2) * 64;   // warp m offset
    const int wn = (warp & 3) * 32;    // warp n offset

    // loader coordinates (2 x 16B per thread for each of A and B)
    const int ar0 = tid >> 2,        ac0 = (tid & 3) << 2;        // A: row 0..63, col0
    const int ar1 = (tid + 256) >> 2;                             // A: row 64..127
    const int br0 = tid >> 5,        bc0 = (tid & 31) << 2;       // B: row 0..7
    const int br1 = (tid + 256) >> 5;                             // B: row 8..15

    float acc[4][4][4];
#pragma unroll
    for (int mi = 0; mi < 4; mi++)
#pragma unroll
        for (int ni = 0; ni < 4; ni++)
#pragma unroll
            for (int r = 0; r < 4; r++) acc[mi][ni][r] = 0.0f;

    const int ntiles = K >> 4;

    // prologue: load tile 0
    {
        cp_async16(&As[0][ar0][ac0], A + (size_t)(bm + ar0) * K + ac0);
        cp_async16(&As[0][ar1][ac0], A + (size_t)(bm + ar1) * K + ac0);
        cp_async16(&Bs[0][br0][bc0], B + (size_t)br0 * N + bn + bc0);
        cp_async16(&Bs[0][br1][bc0], B + (size_t)br1 * N + bn + bc0);
        asm volatile("cp.async.commit_group;\n");
    }

    for (int t = 0; t < ntiles; t++) {
        const int buf = t & 1;
        if (t + 1 < ntiles) {
            const int nb = (t + 1) & 1;
            const int kof = (t + 1) << 4;
            cp_async16(&As[nb][ar0][ac0], A + (size_t)(bm + ar0) * K + kof + ac0);
            cp_async16(&As[nb][ar1][ac0], A + (size_t)(bm + ar1) * K + kof + ac0);
            cp_async16(&Bs[nb][br0][bc0], B + (size_t)(kof + br0) * N + bn + bc0);
            cp_async16(&Bs[nb][br1][bc0], B + (size_t)(kof + br1) * N + bn + bc0);
            asm volatile("cp.async.commit_group;\n");
            asm volatile("cp.async.wait_group 1;\n");
        } else {
            asm volatile("cp.async.wait_group 0;\n");
        }
        __syncthreads();

#pragma unroll
        for (int ks = 0; ks < 2; ks++) {
            const int k0 = ks << 3;
            uint32_t af[4][4], bf[4][2];
#pragma unroll
            for (int mi = 0; mi < 4; mi++) {
                const int row = wm + mi * 16 + g;
                af[mi][0] = f2tf(As[buf][row    ][k0 + c    ]);
                af[mi][1] = f2tf(As[buf][row + 8][k0 + c    ]);
                af[mi][2] = f2tf(As[buf][row    ][k0 + c + 4]);
                af[mi][3] = f2tf(As[buf][row + 8][k0 + c + 4]);
            }
#pragma unroll
            for (int ni = 0; ni < 4; ni++) {
                const int col = wn + ni * 8 + g;
                bf[ni][0] = f2tf(Bs[buf][k0 + c    ][col]);
                bf[ni][1] = f2tf(Bs[buf][k0 + c + 4][col]);
            }
#pragma unroll
            for (int mi = 0; mi < 4; mi++)
#pragma unroll
                for (int ni = 0; ni < 4; ni++)
                    mma_tf32(acc[mi][ni], af[mi], bf[ni]);
        }
        __syncthreads();
    }

    // epilogue
#pragma unroll
    for (int mi = 0; mi < 4; mi++) {
#pragma unroll
        for (int ni = 0; ni < 4; ni++) {
            const int row = bm + wm + mi * 16 + g;
            const int col = bn + wn + ni * 8 + 2 * c;
            const size_t o0 = (size_t)row * N + col;
            const size_t o1 = (size_t)(row + 8) * N + col;
            float2 v0 = make_float2(acc[mi][ni][0], acc[mi][ni][1]);
            float2 v1 = make_float2(acc[mi][ni][2], acc[mi][ni][3]);
            if (EPI == 1) {
                float2 r0 = *(const float2*)(R + o0);
                float2 r1 = *(const float2*)(R + o1);
                v0.x += r0.x; v0.y += r0.y;
                v1.x += r1.x; v1.y += r1.y;
            }
            *(float2*)(C + o0) = v0;
            *(float2*)(C + o1) = v1;
        }
    }
}

// ---------------- RoPE (in-place on q and k heads of qkv) ----------------
__global__ void rope_kernel(float* __restrict__ qkv, const int* __restrict__ pos) {
    const int t  = blockIdx.x;       // 0..NT-1
    const int hh = blockIdx.y;       // 0..NH+NKV-1 (q heads then k heads; offsets contiguous)
    const int i  = threadIdx.x;      // 0..63
    const float p = (float)pos[t & (SEQ - 1)];
    const float inv_freq = powf(10000.0f, -((float)i) / 64.0f);
    float sn, cs;
    sincosf(p * inv_freq, &sn, &cs);
    float* vp = qkv + (size_t)t * QKV_N + hh * HD;
    const float t1 = vp[i];
    const float t2 = vp[i + 64];
    vp[i]      = t1 * cs - t2 * sn;
    vp[i + 64] = t2 * cs + t1 * sn;
}

// ---------------- Flash attention (fp32, causal, GQA) ----------------
// grid (SEQ/64, NH, NB), 256 threads. BM=BN=64, D=128.
#define ATT_SMEM ((3 * 64 * 128 + 64 * 64 + 3 * 64) * 4)

__global__ void __launch_bounds__(256) attn_kernel(const float* __restrict__ qkv,
                                                   float* __restrict__ aout) {
    const int qt = blockIdx.x, h = blockIdx.y, b = blockIdx.z;
    const int kvh = h >> 2;

    extern __shared__ float sm[];
    float* Qs   = sm;                 // [64][128] row-major
    float* Kst  = Qs + 64 * 128;      // [128][64] (d-major, transposed)
    float* Vs   = Kst + 128 * 64;     // [64][128] row-major
    float* Ss   = Vs + 64 * 128;      // [64][64] scores / probs
    float* rowm = Ss + 64 * 64;       // [64]
    float* rowl = rowm + 64;          // [64]
    float* rowa = rowl + 64;          // [64]

    const int tid = threadIdx.x;
    const int q0 = qt * 64;

    // load Q tile
    for (int i = tid; i < 64 * 32; i += 256) {
        int r = i >> 5, c4 = i & 31;
        *(float4*)&Qs[r * 128 + c4 * 4] =
            *(const float4*)(qkv + (size_t)(b * SEQ + q0 + r) * QKV_N + h * HD + c4 * 4);
    }
    if (tid < 64) { rowm[tid] = NEGF; rowl[tid] = 0.0f; }

    const int ty = tid >> 4, tx = tid & 15;
    const int r0 = ty * 4;
    float o[4][8];
#pragma unroll
    for (int a = 0; a < 4; a++)
#pragma unroll
        for (int j = 0; j < 8; j++) o[a][j] = 0.0f;
    __syncthreads();

    const float scale = 0.0883883476483184f;   // 1/sqrt(128)

    for (int kt = 0; kt <= qt; kt++) {
        const int k0 = kt * 64;
        // K tile transposed -> Kst[d][n]
        for (int i = tid; i < 2048; i += 256) {
            int r = i & 63, c4 = i >> 6;
            float4 kk = *(const float4*)(qkv + (size_t)(b * SEQ + k0 + r) * QKV_N
                                         + NH * HD + kvh * HD + c4 * 4);
            int d0 = c4 * 4;
            Kst[(d0 + 0) * 64 + r] = kk.x;
            Kst[(d0 + 1) * 64 + r] = kk.y;
            Kst[(d0 + 2) * 64 + r] = kk.z;
            Kst[(d0 + 3) * 64 + r] = kk.w;
        }
        // V tile row-major
        for (int i = tid; i < 2048; i += 256) {
            int r = i >> 5, c4 = i & 31;
            *(float4*)&Vs[r * 128 + c4 * 4] =
                *(const float4*)(qkv + (size_t)(b * SEQ + k0 + r) * QKV_N
                                 + (NH + NKV) * HD + kvh * HD + c4 * 4);
        }
        __syncthreads();

        // scores: each thread computes 4x4 block (rows r0.., cols tx*4..)
        float s[4][4];
#pragma unroll
        for (int a = 0; a < 4; a++)
#pragma unroll
            for (int j = 0; j < 4; j++) s[a][j] = 0.0f;

#pragma unroll 4
        for (int k = 0; k < 128; k++) {
            float qa[4], kb[4];
#pragma unroll
            for (int a = 0; a < 4; a++) qa[a] = Qs[(r0 + a) * 128 + k];
#pragma unroll
            for (int j = 0; j < 4; j++) kb[j] = Kst[k * 64 + tx * 4 + j];
#pragma unroll
            for (int a = 0; a < 4; a++)
#pragma unroll
                for (int j = 0; j < 4; j++) s[a][j] += qa[a] * kb[j];
        }
        const bool diag = (kt == qt);
#pragma unroll
        for (int a = 0; a < 4; a++)
#pragma unroll
            for (int j = 0; j < 4; j++) {
                float v = s[a][j] * scale;
                if (diag && (r0 + a) < (tx * 4 + j)) v = NEGF;
                Ss[(r0 + a) * 64 + tx * 4 + j] = v;
            }
        __syncthreads();

        // online softmax row update: 4 threads per row
        {
            const int row = tid >> 2, l4 = tid & 3;
            float mx = NEGF;
            for (int c = l4; c < 64; c += 4) mx = fmaxf(mx, Ss[row * 64 + c]);
            mx = fmaxf(mx, __shfl_xor_sync(0xffffffffu, mx, 1));
            mx = fmaxf(mx, __shfl_xor_sync(0xffffffffu, mx, 2));
            const float mold = rowm[row];
            const float mnew = fmaxf(mold, mx);
            float ls = 0.0f;
            for (int c = l4; c < 64; c += 4) {
                float p = expf(Ss[row * 64 + c] - mnew);
                Ss[row * 64 + c] = p;
                ls += p;
            }
            ls += __shfl_xor_sync(0xffffffffu, ls, 1);
            ls += __shfl_xor_sync(0xffffffffu, ls, 2);
            if (l4 == 0) {
                const float alpha = expf(mold - mnew);
                rowa[row] = alpha;
                rowl[row] = rowl[row] * alpha + ls;
                rowm[row] = mnew;
            }
        }
        __syncthreads();

        // rescale o, accumulate P@V (rows r0.., cols tx*8..)
        float al[4];
#pragma unroll
        for (int a = 0; a < 4; a++) al[a] = rowa[r0 + a];
#pragma unroll
        for (int a = 0; a < 4; a++)
#pragma unroll
            for (int j = 0; j < 8; j++) o[a][j] *= al[a];

#pragma unroll 2
        for (int kk = 0; kk < 64; kk++) {
            float p[4];
#pragma unroll
            for (int a = 0; a < 4; a++) p[a] = Ss[(r0 + a) * 64 + kk];
            float4 v0 = *(const float4*)&Vs[kk * 128 + tx * 8];
            float4 v1 = *(const float4*)&Vs[kk * 128 + tx * 8 + 4];
            float vv[8] = {v0.x, v0.y, v0.z, v0.w, v1.x, v1.y, v1.z, v1.w};
#pragma unroll
            for (int a = 0; a < 4; a++)
#pragma unroll
                for (int j = 0; j < 8; j++) o[a][j] += p[a] * vv[j];
        }
        __syncthreads();
    }

    // normalize & write: aout[t][h*128 + d]
    float il[4];
#pragma unroll
    for (int a = 0; a < 4; a++) il[a] = 1.0f / rowl[r0 + a];
#pragma unroll
    for (int a = 0; a < 4; a++) {
        size_t off = (size_t)(b * SEQ + q0 + r0 + a) * HID + h * HD + tx * 8;
        float4 o0 = make_float4(o[a][0] * il[a], o[a][1] * il[a], o[a][2] * il[a], o[a][3] * il[a]);
        float4 o1 = make_float4(o[a][4] * il[a], o[a][5] * il[a], o[a][6] * il[a], o[a][7] * il[a]);
        *(float4*)(aout + off)     = o0;
        *(float4*)(aout + off + 4) = o1;
    }
}

// ---------------- SiLU(gate)*up ----------------
__global__ void __launch_bounds__(256) silu_kernel(const float* __restrict__ gu,
                                                   float* __restrict__ act) {
    size_t idx = (size_t)blockIdx.x * 256 + threadIdx.x;   // over NT*FFI/4
    int row = (int)(idx / (FFI / 4));
    int c   = (int)(idx % (FFI / 4));
    const float4 g = *(const float4*)(gu + (size_t)row * 2 * FFI + c * 4);
    const float4 u = *(const float4*)(gu + (size_t)row * 2 * FFI + FFI + c * 4);
    float4 r;
    r.x = g.x / (1.0f + expf(-g.x)) * u.x;
    r.y = g.y / (1.0f + expf(-g.y)) * u.y;
    r.z = g.z / (1.0f + expf(-g.z)) * u.z;
    r.w = g.w / (1.0f + expf(-g.w)) * u.w;
    *(float4*)(act + (size_t)row * FFI + c * 4) = r;
}

// ---------------- launch ----------------
extern "C" void kernel_launch(void* const* d_in, const int* in_sizes, int n_in,
                              void* d_out, int out_size) {
    const float* x    = (const float*)d_in[0];
    const float* ln1w = (const float*)d_in[1];
    const float* wqkv = (const float*)d_in[2];
    const float* wo   = (const float*)d_in[3];
    const float* ln2w = (const float*)d_in[4];
    const float* wgu  = (const float*)d_in[5];
    const float* wdn  = (const float*)d_in[6];
    const int*   pos  = (const int*)d_in[7];
    float* out = (float*)d_out;

    void *ph, *pqkv, *paout, *ph1, *ph2, *pgu, *pact;
    cudaGetSymbolAddress(&ph,    g_h);
    cudaGetSymbolAddress(&pqkv,  g_qkv);
    cudaGetSymbolAddress(&paout, g_aout);
    cudaGetSymbolAddress(&ph1,   g_h1);
    cudaGetSymbolAddress(&ph2,   g_h2);
    cudaGetSymbolAddress(&pgu,   g_gu);
    cudaGetSymbolAddress(&pact,  g_act);
    float* h    = (float*)ph;
    float* qkv  = (float*)pqkv;
    float* aout = (float*)paout;
    float* h1   = (float*)ph1;
    float* h2   = (float*)ph2;
    float* gu   = (float*)pgu;
    float* act  = (float*)pact;

    cudaFuncSetAttribute(attn_kernel, cudaFuncAttributeMaxDynamicSharedMemorySize, ATT_SMEM);

    // 1. h = rmsnorm(x, ln1_w)
    rmsnorm_kernel<<<NT, 256>>>(x, ln1w, h);
    // 2. qkv = h @ wqkv   (tensor cores, tf32)
    tf32gemm_kernel<0><<<dim3(QKV_N / 128, NT / 128), 256>>>(h, wqkv, nullptr, qkv, NT, QKV_N, HID);
    // 3. rope(q, k)
    rope_kernel<<<dim3(NT, NH + NKV), 64>>>(qkv, pos);
    // 4. flash attention -> aout
    attn_kernel<<<dim3(SEQ / 64, NH, NB), 256, ATT_SMEM>>>(qkv, aout);
    // 5. h1 = x + aout @ wo
    tf32gemm_kernel<1><<<dim3(HID / 128, NT / 128), 256>>>(aout, wo, x, h1, NT, HID, HID);
    // 6. h2 = rmsnorm(h1, ln2_w)
    rmsnorm_kernel<<<NT, 256>>>(h1, ln2w, h2);
    // 7. gu = h2 @ w_gate_up
    tf32gemm_kernel<0><<<dim3(2 * FFI / 128, NT / 128), 256>>>(h2, wgu, nullptr, gu, NT, 2 * FFI, HID);
    // 8. act = silu(gate) * up
    silu_kernel<<<(NT * FFI / 4) / 256, 256>>>(gu, act);
    // 9. out = h1 + act @ w_down
    tf32gemm_kernel<1><<<dim3(HID / 128, NT / 128), 256>>>(act, wdn, h1, out, NT, HID, FFI);
}

// round 4
// speedup vs baseline: 3.1053x; 1.5481x over previous
#include <cuda_runtime.h>
#include <math.h>
#include <stdint.h>

// Problem constants
#define HID   2048
#define NH    16
#define NKV   4
#define HD    128
#define SEQ   1024
#define NB    4
#define NT    4096          // NB*SEQ tokens
#define QKV_N 3072          // (NH + 2*NKV) * HD
#define FFI   8192
#define EPS   1e-6f
#define NEGF  (-1e30f)

// ---------------- scratch (no allocations allowed) ----------------
__device__ float g_h   [(size_t)NT * HID];     // rmsnorm1 output
__device__ float g_qkv [(size_t)NT * QKV_N];   // qkv projection
__device__ float g_aout[(size_t)NT * HID];     // attention output (B,S,H*D)
__device__ float g_h1  [(size_t)NT * HID];     // x + attn@wo
__device__ float g_h2  [(size_t)NT * HID];     // rmsnorm2 output
__device__ float g_gu  [(size_t)NT * 2 * FFI]; // gate/up projection
__device__ float g_act [(size_t)NT * FFI];     // silu(gate)*up

// ---------------- helpers ----------------
__device__ __forceinline__ uint32_t f2tf(float f) {
    uint32_t u;
    asm("cvt.rna.tf32.f32 %0, %1;" : "=r"(u) : "f"(f));
    return u;
}

__device__ __forceinline__ void mma_tf32(float* d, const uint32_t* a, const uint32_t* b) {
    asm volatile(
        "mma.sync.aligned.m16n8k8.row.col.f32.tf32.tf32.f32 "
        "{%0,%1,%2,%3}, {%4,%5,%6,%7}, {%8,%9}, {%0,%1,%2,%3};\n"
        : "+f"(d[0]), "+f"(d[1]), "+f"(d[2]), "+f"(d[3])
        : "r"(a[0]), "r"(a[1]), "r"(a[2]), "r"(a[3]), "r"(b[0]), "r"(b[1]));
}

__device__ __forceinline__ void cp_async16(void* s, const void* g) {
    uint32_t sa = (uint32_t)__cvta_generic_to_shared(s);
    asm volatile("cp.async.cg.shared.global [%0], [%1], 16;\n" :: "r"(sa), "l"(g));
}

// ---------------- RMSNorm ----------------
__global__ void __launch_bounds__(256) rmsnorm_kernel(const float* __restrict__ x,
                                                      const float* __restrict__ w,
                                                      float* __restrict__ out) {
    const int row = blockIdx.x;
    const int tid = threadIdx.x;
    const float4* xr = (const float4*)(x + (size_t)row * HID);
    const float4* wr = (const float4*)w;
    float4* orow = (float4*)(out + (size_t)row * HID);

    float4 v0 = xr[tid];
    float4 v1 = xr[tid + 256];
    float ss = v0.x*v0.x + v0.y*v0.y + v0.z*v0.z + v0.w*v0.w
             + v1.x*v1.x + v1.y*v1.y + v1.z*v1.z + v1.w*v1.w;

    __shared__ float red[256];
    red[tid] = ss;
    __syncthreads();
    for (int s = 128; s > 0; s >>= 1) {
        if (tid < s) red[tid] += red[tid + s];
        __syncthreads();
    }
    const float inv = rsqrtf(red[0] * (1.0f / HID) + EPS);

    float4 w0 = wr[tid], w1 = wr[tid + 256];
    float4 o0 = make_float4(v0.x*inv*w0.x, v0.y*inv*w0.y, v0.z*inv*w0.z, v0.w*inv*w0.w);
    float4 o1 = make_float4(v1.x*inv*w1.x, v1.y*inv*w1.y, v1.z*inv*w1.z, v1.w*inv*w1.w);
    orow[tid]       = o0;
    orow[tid + 256] = o1;
}

// ---------------- TF32 tensor-core GEMM ----------------
// C[M,N] = A[M,K] @ B[K,N] (+R).  128x128 block, BK=16, 256 threads.
// 8 warps in 2x4 (m x n) grid, each warp owns a 64x32 tile =
// 4x4 grid of m16n8k8 mma fragments. cp.async double buffering.
template <int EPI>
__global__ void __launch_bounds__(256) tf32gemm_kernel(const float* __restrict__ A,
                                                       const float* __restrict__ B,
                                                       const float* __restrict__ R,
                                                       float* __restrict__ C,
                                                       int M, int N, int K) {
    __shared__ float As[2][128][20];   // [m][k], pitch 20 -> conflict-free frag loads
    __shared__ float Bs[2][16][136];   // [k][n], pitch 136 -> conflict-free frag loads

    const int tid  = threadIdx.x;
    const int bm   = blockIdx.y * 128;
    const int bn   = blockIdx.x * 128;
    const int lane = tid & 31;
    const int warp = tid >> 5;
    const int g = lane >> 2;           // group id 0..7
    const int c = lane & 3;            // thread-in-group 0..3
    const int wm = (warp >> 2) * 64;   // warp m offset
    const int wn = (warp & 3) * 32;    // warp n offset

    // loader coordinates (2 x 16B per thread for each of A and B)
    const int ar0 = tid >> 2,        ac0 = (tid & 3) << 2;        // A: row 0..63, col0
    const int ar1 = (tid + 256) >> 2;                             // A: row 64..127
    const int br0 = tid >> 5,        bc0 = (tid & 31) << 2;       // B: row 0..7
    const int br1 = (tid + 256) >> 5;                             // B: row 8..15

    float acc[4][4][4];
#pragma unroll
    for (int mi = 0; mi < 4; mi++)
#pragma unroll
        for (int ni = 0; ni < 4; ni++)
#pragma unroll
            for (int r = 0; r < 4; r++) acc[mi][ni][r] = 0.0f;

    const int ntiles = K >> 4;

    // prologue: load tile 0
    {
        cp_async16(&As[0][ar0][ac0], A + (size_t)(bm + ar0) * K + ac0);
        cp_async16(&As[0][ar1][ac0], A + (size_t)(bm + ar1) * K + ac0);
        cp_async16(&Bs[0][br0][bc0], B + (size_t)br0 * N + bn + bc0);
        cp_async16(&Bs[0][br1][bc0], B + (size_t)br1 * N + bn + bc0);
        asm volatile("cp.async.commit_group;\n");
    }

    for (int t = 0; t < ntiles; t++) {
        const int buf = t & 1;
        if (t + 1 < ntiles) {
            const int nb = (t + 1) & 1;
            const int kof = (t + 1) << 4;
            cp_async16(&As[nb][ar0][ac0], A + (size_t)(bm + ar0) * K + kof + ac0);
            cp_async16(&As[nb][ar1][ac0], A + (size_t)(bm + ar1) * K + kof + ac0);
            cp_async16(&Bs[nb][br0][bc0], B + (size_t)(kof + br0) * N + bn + bc0);
            cp_async16(&Bs[nb][br1][bc0], B + (size_t)(kof + br1) * N + bn + bc0);
            asm volatile("cp.async.commit_group;\n");
            asm volatile("cp.async.wait_group 1;\n");
        } else {
            asm volatile("cp.async.wait_group 0;\n");
        }
        __syncthreads();

#pragma unroll
        for (int ks = 0; ks < 2; ks++) {
            const int k0 = ks << 3;
            uint32_t af[4][4], bf[4][2];
#pragma unroll
            for (int mi = 0; mi < 4; mi++) {
                const int row = wm + mi * 16 + g;
                af[mi][0] = f2tf(As[buf][row    ][k0 + c    ]);
                af[mi][1] = f2tf(As[buf][row + 8][k0 + c    ]);
                af[mi][2] = f2tf(As[buf][row    ][k0 + c + 4]);
                af[mi][3] = f2tf(As[buf][row + 8][k0 + c + 4]);
            }
#pragma unroll
            for (int ni = 0; ni < 4; ni++) {
                const int col = wn + ni * 8 + g;
                bf[ni][0] = f2tf(Bs[buf][k0 + c    ][col]);
                bf[ni][1] = f2tf(Bs[buf][k0 + c + 4][col]);
            }
#pragma unroll
            for (int mi = 0; mi < 4; mi++)
#pragma unroll
                for (int ni = 0; ni < 4; ni++)
                    mma_tf32(acc[mi][ni], af[mi], bf[ni]);
        }
        __syncthreads();
    }

    // epilogue
#pragma unroll
    for (int mi = 0; mi < 4; mi++) {
#pragma unroll
        for (int ni = 0; ni < 4; ni++) {
            const int row = bm + wm + mi * 16 + g;
            const int col = bn + wn + ni * 8 + 2 * c;
            const size_t o0 = (size_t)row * N + col;
            const size_t o1 = (size_t)(row + 8) * N + col;
            float2 v0 = make_float2(acc[mi][ni][0], acc[mi][ni][1]);
            float2 v1 = make_float2(acc[mi][ni][2], acc[mi][ni][3]);
            if (EPI == 1) {
                float2 r0 = *(const float2*)(R + o0);
                float2 r1 = *(const float2*)(R + o1);
                v0.x += r0.x; v0.y += r0.y;
                v1.x += r1.x; v1.y += r1.y;
            }
            *(float2*)(C + o0) = v0;
            *(float2*)(C + o1) = v1;
        }
    }
}

// ---------------- RoPE (in-place on q and k heads of qkv) ----------------
__global__ void rope_kernel(float* __restrict__ qkv, const int* __restrict__ pos) {
    const int t  = blockIdx.x;       // 0..NT-1
    const int hh = blockIdx.y;       // 0..NH+NKV-1 (q heads then k heads; offsets contiguous)
    const int i  = threadIdx.x;      // 0..63
    const float p = (float)pos[t & (SEQ - 1)];
    const float inv_freq = powf(10000.0f, -((float)i) / 64.0f);
    float sn, cs;
    sincosf(p * inv_freq, &sn, &cs);
    float* vp = qkv + (size_t)t * QKV_N + hh * HD;
    const float t1 = vp[i];
    const float t2 = vp[i + 64];
    vp[i]      = t1 * cs - t2 * sn;
    vp[i + 64] = t2 * cs + t1 * sn;
}

// ---------------- Flash attention (fp32, causal, GQA) ----------------
// grid (SEQ/64, NH, NB), 256 threads. BM=BN=64, D=128.
#define ATT_SMEM ((3 * 64 * 128 + 64 * 64 + 3 * 64) * 4)

__global__ void __launch_bounds__(256) attn_kernel(const float* __restrict__ qkv,
                                                   float* __restrict__ aout) {
    const int qt = blockIdx.x, h = blockIdx.y, b = blockIdx.z;
    const int kvh = h >> 2;

    extern __shared__ float sm[];
    float* Qs   = sm;                 // [64][128] row-major
    float* Kst  = Qs + 64 * 128;      // [128][64] (d-major, transposed)
    float* Vs   = Kst + 128 * 64;     // [64][128] row-major
    float* Ss   = Vs + 64 * 128;      // [64][64] scores / probs
    float* rowm = Ss + 64 * 64;       // [64]
    float* rowl = rowm + 64;          // [64]
    float* rowa = rowl + 64;          // [64]

    const int tid = threadIdx.x;
    const int q0 = qt * 64;

    // load Q tile
    for (int i = tid; i < 64 * 32; i += 256) {
        int r = i >> 5, c4 = i & 31;
        *(float4*)&Qs[r * 128 + c4 * 4] =
            *(const float4*)(qkv + (size_t)(b * SEQ + q0 + r) * QKV_N + h * HD + c4 * 4);
    }
    if (tid < 64) { rowm[tid] = NEGF; rowl[tid] = 0.0f; }

    const int ty = tid >> 4, tx = tid & 15;
    const int r0 = ty * 4;
    float o[4][8];
#pragma unroll
    for (int a = 0; a < 4; a++)
#pragma unroll
        for (int j = 0; j < 8; j++) o[a][j] = 0.0f;
    __syncthreads();

    const float scale = 0.0883883476483184f;   // 1/sqrt(128)

    for (int kt = 0; kt <= qt; kt++) {
        const int k0 = kt * 64;
        // K tile transposed -> Kst[d][n]
        for (int i = tid; i < 2048; i += 256) {
            int r = i & 63, c4 = i >> 6;
            float4 kk = *(const float4*)(qkv + (size_t)(b * SEQ + k0 + r) * QKV_N
                                         + NH * HD + kvh * HD + c4 * 4);
            int d0 = c4 * 4;
            Kst[(d0 + 0) * 64 + r] = kk.x;
            Kst[(d0 + 1) * 64 + r] = kk.y;
            Kst[(d0 + 2) * 64 + r] = kk.z;
            Kst[(d0 + 3) * 64 + r] = kk.w;
        }
        // V tile row-major
        for (int i = tid; i < 2048; i += 256) {
            int r = i >> 5, c4 = i & 31;
            *(float4*)&Vs[r * 128 + c4 * 4] =
                *(const float4*)(qkv + (size_t)(b * SEQ + k0 + r) * QKV_N
                                 + (NH + NKV) * HD + kvh * HD + c4 * 4);
        }
        __syncthreads();

        // scores: each thread computes 4x4 block (rows r0.., cols tx*4..)
        float s[4][4];
#pragma unroll
        for (int a = 0; a < 4; a++)
#pragma unroll
            for (int j = 0; j < 4; j++) s[a][j] = 0.0f;

#pragma unroll 4
        for (int k = 0; k < 128; k++) {
            float qa[4], kb[4];
#pragma unroll
            for (int a = 0; a < 4; a++) qa[a] = Qs[(r0 + a) * 128 + k];
#pragma unroll
            for (int j = 0; j < 4; j++) kb[j] = Kst[k * 64 + tx * 4 + j];
#pragma unroll
            for (int a = 0; a < 4; a++)
#pragma unroll
                for (int j = 0; j < 4; j++) s[a][j] += qa[a] * kb[j];
        }
        const bool diag = (kt == qt);
#pragma unroll
        for (int a = 0; a < 4; a++)
#pragma unroll
            for (int j = 0; j < 4; j++) {
                float v = s[a][j] * scale;
                if (diag && (r0 + a) < (tx * 4 + j)) v = NEGF;
                Ss[(r0 + a) * 64 + tx * 4 + j] = v;
            }
        __syncthreads();

        // online softmax row update: 4 threads per row
        {
            const int row = tid >> 2, l4 = tid & 3;
            float mx = NEGF;
            for (int c = l4; c < 64; c += 4) mx = fmaxf(mx, Ss[row * 64 + c]);
            mx = fmaxf(mx, __shfl_xor_sync(0xffffffffu, mx, 1));
            mx = fmaxf(mx, __shfl_xor_sync(0xffffffffu, mx, 2));
            const float mold = rowm[row];
            const float mnew = fmaxf(mold, mx);
            float ls = 0.0f;
            for (int c = l4; c < 64; c += 4) {
                float p = expf(Ss[row * 64 + c] - mnew);
                Ss[row * 64 + c] = p;
                ls += p;
            }
            ls += __shfl_xor_sync(0xffffffffu, ls, 1);
            ls += __shfl_xor_sync(0xffffffffu, ls, 2);
            if (l4 == 0) {
                const float alpha = expf(mold - mnew);
                rowa[row] = alpha;
                rowl[row] = rowl[row] * alpha + ls;
                rowm[row] = mnew;
            }
        }
        __syncthreads();

        // rescale o, accumulate P@V (rows r0.., cols tx*8..)
        float al[4];
#pragma unroll
        for (int a = 0; a < 4; a++) al[a] = rowa[r0 + a];
#pragma unroll
        for (int a = 0; a < 4; a++)
#pragma unroll
            for (int j = 0; j < 8; j++) o[a][j] *= al[a];

#pragma unroll 2
        for (int kk = 0; kk < 64; kk++) {
            float p[4];
#pragma unroll
            for (int a = 0; a < 4; a++) p[a] = Ss[(r0 + a) * 64 + kk];
            float4 v0 = *(const float4*)&Vs[kk * 128 + tx * 8];
            float4 v1 = *(const float4*)&Vs[kk * 128 + tx * 8 + 4];
            float vv[8] = {v0.x, v0.y, v0.z, v0.w, v1.x, v1.y, v1.z, v1.w};
#pragma unroll
            for (int a = 0; a < 4; a++)
#pragma unroll
                for (int j = 0; j < 8; j++) o[a][j] += p[a] * vv[j];
        }
        __syncthreads();
    }

    // normalize & write: aout[t][h*128 + d]
    float il[4];
#pragma unroll
    for (int a = 0; a < 4; a++) il[a] = 1.0f / rowl[r0 + a];
#pragma unroll
    for (int a = 0; a < 4; a++) {
        size_t off = (size_t)(b * SEQ + q0 + r0 + a) * HID + h * HD + tx * 8;
        float4 o0 = make_float4(o[a][0] * il[a], o[a][1] * il[a], o[a][2] * il[a], o[a][3] * il[a]);
        float4 o1 = make_float4(o[a][4] * il[a], o[a][5] * il[a], o[a][6] * il[a], o[a][7] * il[a]);
        *(float4*)(aout + off)     = o0;
        *(float4*)(aout + off + 4) = o1;
    }
}

// ---------------- SiLU(gate)*up ----------------
__global__ void __launch_bounds__(256) silu_kernel(const float* __restrict__ gu,
                                                   float* __restrict__ act) {
    size_t idx = (size_t)blockIdx.x * 256 + threadIdx.x;   // over NT*FFI/4
    int row = (int)(idx / (FFI / 4));
    int c   = (int)(idx % (FFI / 4));
    const float4 g = *(const float4*)(gu + (size_t)row * 2 * FFI + c * 4);
    const float4 u = *(const float4*)(gu + (size_t)row * 2 * FFI + FFI + c * 4);
    float4 r;
    r.x = g.x / (1.0f + expf(-g.x)) * u.x;
    r.y = g.y / (1.0f + expf(-g.y)) * u.y;
    r.z = g.z / (1.0f + expf(-g.z)) * u.z;
    r.w = g.w / (1.0f + expf(-g.w)) * u.w;
    *(float4*)(act + (size_t)row * FFI + c * 4) = r;
}

// ---------------- launch ----------------
extern "C" void kernel_launch(void* const* d_in, const int* in_sizes, int n_in,
                              void* d_out, int out_size) {
    const float* x    = (const float*)d_in[0];
    const float* ln1w = (const float*)d_in[1];
    const float* wqkv = (const float*)d_in[2];
    const float* wo   = (const float*)d_in[3];
    const float* ln2w = (const float*)d_in[4];
    const float* wgu  = (const float*)d_in[5];
    const float* wdn  = (const float*)d_in[6];
    const int*   pos  = (const int*)d_in[7];
    float* out = (float*)d_out;

    void *ph, *pqkv, *paout, *ph1, *ph2, *pgu, *pact;
    cudaGetSymbolAddress(&ph,    g_h);
    cudaGetSymbolAddress(&pqkv,  g_qkv);
    cudaGetSymbolAddress(&paout, g_aout);
    cudaGetSymbolAddress(&ph1,   g_h1);
    cudaGetSymbolAddress(&ph2,   g_h2);
    cudaGetSymbolAddress(&pgu,   g_gu);
    cudaGetSymbolAddress(&pact,  g_act);
    float* h    = (float*)ph;
    float* qkv  = (float*)pqkv;
    float* aout = (float*)paout;
    float* h1   = (float*)ph1;
    float* h2   = (float*)ph2;
    float* gu   = (float*)pgu;
    float* act  = (float*)pact;

    cudaFuncSetAttribute(attn_kernel, cudaFuncAttributeMaxDynamicSharedMemorySize, ATT_SMEM);

    // 1. h = rmsnorm(x, ln1_w)
    rmsnorm_kernel<<<NT, 256>>>(x, ln1w, h);
    // 2. qkv = h @ wqkv   (tensor cores, tf32)
    tf32gemm_kernel<0><<<dim3(QKV_N / 128, NT / 128), 256>>>(h, wqkv, nullptr, qkv, NT, QKV_N, HID);
    // 3. rope(q, k)
    rope_kernel<<<dim3(NT, NH + NKV), 64>>>(qkv, pos);
    // 4. flash attention -> aout
    attn_kernel<<<dim3(SEQ / 64, NH, NB), 256, ATT_SMEM>>>(qkv, aout);
    // 5. h1 = x + aout @ wo
    tf32gemm_kernel<1><<<dim3(HID / 128, NT / 128), 256>>>(aout, wo, x, h1, NT, HID, HID);
    // 6. h2 = rmsnorm(h1, ln2_w)
    rmsnorm_kernel<<<NT, 256>>>(h1, ln2w, h2);
    // 7. gu = h2 @ w_gate_up
    tf32gemm_kernel<0><<<dim3(2 * FFI / 128, NT / 128), 256>>>(h2, wgu, nullptr, gu, NT, 2 * FFI, HID);
    // 8. act = silu(gate) * up
    silu_kernel<<<(NT * FFI / 4) / 256, 256>>>(gu, act);
    // 9. out = h1 + act @ w_down
    tf32gemm_kernel<1><<<dim3(HID / 128, NT / 128), 256>>>(act, wdn, h1, out, NT, HID, FFI);
}